// round 1
// baseline (speedup 1.0000x reference)
#include <cuda_runtime.h>
#include <cstdint>

#define N_USERS     50000
#define N_ENTITIES  100000
#define N_RELATIONS 16
#define N_EDGES     3200000
#define NNZ         2500000
#define CH          64
#define N_HOPS      2

// Scratch (allocation-free, __device__ globals). 16B-aligned for float4 / red.v4.
__device__ __align__(16) float g_ent_cur[(size_t)N_ENTITIES * CH];
__device__ __align__(16) float g_ent_agg[(size_t)N_ENTITIES * CH];
__device__ __align__(16) float g_usr_agg[(size_t)N_USERS * CH];

__device__ __forceinline__ void red_add_v4(float* dst, float4 v) {
    asm volatile("red.global.add.v4.f32 [%0], {%1, %2, %3, %4};"
                 :: "l"(dst), "f"(v.x), "f"(v.y), "f"(v.z), "f"(v.w)
                 : "memory");
}

// KG scatter: neigh = ent_cur[tail] * mask * weight[type-1]; red into ent_agg[head].
// 16 threads per edge, one float4 (4 channels) each.
__global__ void kg_scatter_kernel(const float* __restrict__ mask,
                                  const int*   __restrict__ head,
                                  const int*   __restrict__ tail,
                                  const int*   __restrict__ etype,
                                  const float* __restrict__ weight) {
    __shared__ float s_w[N_RELATIONS * CH];
    for (int i = threadIdx.x; i < N_RELATIONS * CH; i += blockDim.x)
        s_w[i] = weight[i];
    __syncthreads();

    unsigned gid = blockIdx.x * blockDim.x + threadIdx.x;
    unsigned e = gid >> 4;
    unsigned sub = gid & 15u;
    if (e >= N_EDGES) return;

    int t = tail[e];
    int h = head[e];
    int r = etype[e] - 1;
    float m = mask[e];

    float4 v = *reinterpret_cast<const float4*>(&g_ent_cur[(size_t)t * CH + sub * 4]);
    float4 w = *reinterpret_cast<const float4*>(&s_w[r * CH + sub * 4]);
    float4 o;
    o.x = v.x * m * w.x;
    o.y = v.y * m * w.y;
    o.z = v.z * m * w.z;
    o.w = v.w * m * w.w;
    red_add_v4(&g_ent_agg[(size_t)h * CH + sub * 4], o);
}

// User scatter: usr_agg[row] += vals * ent_cur[col]. 16 threads per nnz.
__global__ void user_scatter_kernel(const float* __restrict__ vals,
                                    const int*   __restrict__ rows,
                                    const int*   __restrict__ cols) {
    unsigned gid = blockIdx.x * blockDim.x + threadIdx.x;
    unsigned e = gid >> 4;
    unsigned sub = gid & 15u;
    if (e >= NNZ) return;

    int c = cols[e];
    int rw = rows[e];
    float s = vals[e];

    float4 v = *reinterpret_cast<const float4*>(&g_ent_cur[(size_t)c * CH + sub * 4]);
    float4 o;
    o.x = v.x * s; o.y = v.y * s; o.z = v.z * s; o.w = v.w * s;
    red_add_v4(&g_usr_agg[(size_t)rw * CH + sub * 4], o);
}

// Fused: normalize(agg) -> res += n; cur = n (optional); agg = 0 (for next hop).
// One warp per row; float2 per lane (32 lanes * 2 = 64 channels).
__global__ void normalize_acc_kernel(float* __restrict__ agg,
                                     float* __restrict__ res,
                                     float* __restrict__ cur,
                                     int nrows) {
    int warp = (blockIdx.x * blockDim.x + threadIdx.x) >> 5;
    int lane = threadIdx.x & 31;
    if (warp >= nrows) return;

    size_t off = (size_t)warp * CH + lane * 2;
    float2 v = *reinterpret_cast<float2*>(&agg[off]);
    float ss = v.x * v.x + v.y * v.y;
    #pragma unroll
    for (int o = 16; o > 0; o >>= 1)
        ss += __shfl_xor_sync(0xffffffffu, ss, o);
    float inv = 1.0f / fmaxf(sqrtf(ss), 1e-12f);

    float2 n;
    n.x = v.x * inv;
    n.y = v.y * inv;

    float2 r = *reinterpret_cast<float2*>(&res[off]);
    r.x += n.x;
    r.y += n.y;
    *reinterpret_cast<float2*>(&res[off]) = r;

    if (cur) *reinterpret_cast<float2*>(&cur[off]) = n;
    *reinterpret_cast<float2*>(&agg[off]) = make_float2(0.f, 0.f);
}

extern "C" void kernel_launch(void* const* d_in, const int* in_sizes, int n_in,
                              void* d_out, int out_size) {
    const float* user_emb   = (const float*)d_in[0];
    const float* entity_emb = (const float*)d_in[1];
    const float* weight     = (const float*)d_in[2];
    const float* mask       = (const float*)d_in[3];
    const float* ivals      = (const float*)d_in[4];
    const int*   ehead      = (const int*)d_in[5];
    const int*   etail      = (const int*)d_in[6];
    const int*   etype      = (const int*)d_in[7];
    const int*   irows      = (const int*)d_in[8];
    const int*   icols      = (const int*)d_in[9];

    float* out     = (float*)d_out;
    float* ent_res = out;
    float* usr_res = out + (size_t)N_ENTITIES * CH;

    void* p;
    cudaGetSymbolAddress(&p, g_ent_cur); float* ent_cur = (float*)p;
    cudaGetSymbolAddress(&p, g_ent_agg); float* ent_agg = (float*)p;
    cudaGetSymbolAddress(&p, g_usr_agg); float* usr_agg = (float*)p;

    const size_t ent_bytes = (size_t)N_ENTITIES * CH * sizeof(float);
    const size_t usr_bytes = (size_t)N_USERS * CH * sizeof(float);

    // Init: residuals start at raw embeddings; cur = entity_emb; aggs = 0.
    cudaMemcpyAsync(ent_cur, entity_emb, ent_bytes, cudaMemcpyDeviceToDevice);
    cudaMemcpyAsync(ent_res, entity_emb, ent_bytes, cudaMemcpyDeviceToDevice);
    cudaMemcpyAsync(usr_res, user_emb,   usr_bytes, cudaMemcpyDeviceToDevice);
    cudaMemsetAsync(ent_agg, 0, ent_bytes);
    cudaMemsetAsync(usr_agg, 0, usr_bytes);

    const int TPB = 256;
    const unsigned kg_blocks   = (unsigned)(((size_t)N_EDGES * 16 + TPB - 1) / TPB);
    const unsigned usr_blocks  = (unsigned)(((size_t)NNZ * 16 + TPB - 1) / TPB);
    const unsigned ne_blocks   = (N_ENTITIES * 32 + TPB - 1) / TPB;  // 1 warp/row
    const unsigned nu_blocks   = (N_USERS * 32 + TPB - 1) / TPB;

    for (int hop = 0; hop < N_HOPS; hop++) {
        kg_scatter_kernel<<<kg_blocks, TPB>>>(mask, ehead, etail, etype, weight);
        user_scatter_kernel<<<usr_blocks, TPB>>>(ivals, irows, icols);
        // normalize + residual-accumulate + zero agg for next hop
        normalize_acc_kernel<<<ne_blocks, TPB>>>(ent_agg, ent_res, ent_cur, N_ENTITIES);
        normalize_acc_kernel<<<nu_blocks, TPB>>>(usr_agg, usr_res, nullptr, N_USERS);
    }
}

// round 2
// speedup vs baseline: 1.6680x; 1.6680x over previous
#include <cuda_runtime.h>
#include <cstdint>

#define N_USERS     50000
#define N_ENTITIES  100000
#define N_RELATIONS 16
#define N_EDGES     3200000
#define NNZ         2500000
#define CH          64
#define N_HOPS      2

// ---------------- scratch (__device__ globals, allocation-free) ----------------
__device__ __align__(16) float g_ent_next[(size_t)N_ENTITIES * CH];  // hop-0 normalized entity output

__device__ int  g_kg_start[N_ENTITIES + 1];
__device__ int  g_kg_cursor[N_ENTITIES];      // doubles as histogram counts
__device__ int2 g_kg_edges[N_EDGES];          // {tail | rel<<20, mask_bits} grouped by head

__device__ int  g_u_start[N_USERS + 1];
__device__ int  g_u_cursor[N_USERS];
__device__ int2 g_u_edges[NNZ];               // {col, val_bits} grouped by user row

// ---------------- preprocessing: histogram ----------------
__global__ void hist_kernel(const int* __restrict__ idx, int n, int* __restrict__ cnt) {
    int i = blockIdx.x * blockDim.x + threadIdx.x;
    if (i < n) atomicAdd(&cnt[idx[i]], 1);
}

// ---------------- preprocessing: exclusive scan (block 0 -> KG, block 1 -> user) ----------------
__global__ void scan2_kernel() {
    int* cnt   = (blockIdx.x == 0) ? g_kg_cursor : g_u_cursor;
    int* start = (blockIdx.x == 0) ? g_kg_start  : g_u_start;
    int  n     = (blockIdx.x == 0) ? N_ENTITIES  : N_USERS;

    __shared__ int s_wsum[32];
    __shared__ int s_carry;
    int lane = threadIdx.x & 31, wid = threadIdx.x >> 5;
    if (threadIdx.x == 0) s_carry = 0;
    __syncthreads();

    for (int base = 0; base < n; base += 1024) {
        int i = base + threadIdx.x;
        int v = (i < n) ? cnt[i] : 0;
        int x = v;
        #pragma unroll
        for (int off = 1; off < 32; off <<= 1) {
            int y = __shfl_up_sync(0xffffffffu, x, off);
            if (lane >= off) x += y;
        }
        if (lane == 31) s_wsum[wid] = x;
        __syncthreads();
        int carry = s_carry;
        __syncthreads();                    // all reads of s_carry complete
        if (wid == 0) {
            int ws = s_wsum[lane];
            int wx = ws;
            #pragma unroll
            for (int off = 1; off < 32; off <<= 1) {
                int y = __shfl_up_sync(0xffffffffu, wx, off);
                if (lane >= off) wx += y;
            }
            s_wsum[lane] = wx - ws;         // exclusive warp offsets
            if (lane == 31) s_carry = carry + wx;
        }
        __syncthreads();
        int excl = carry + s_wsum[wid] + x - v;
        if (i < n) { start[i] = excl; cnt[i] = excl; }   // cnt becomes cursor
        __syncthreads();                    // protect s_wsum before next chunk
    }
    if (threadIdx.x == 0) start[n] = s_carry;
}

// ---------------- preprocessing: bucket-scatter into grouped edge records ----------------
__global__ void kg_build_kernel(const int* __restrict__ head, const int* __restrict__ tail,
                                const int* __restrict__ etype, const float* __restrict__ mask) {
    int e = blockIdx.x * blockDim.x + threadIdx.x;
    if (e >= N_EDGES) return;
    int idx = atomicAdd(&g_kg_cursor[head[e]], 1);
    g_kg_edges[idx] = make_int2(tail[e] | ((etype[e] - 1) << 20), __float_as_int(mask[e]));
}

__global__ void u_build_kernel(const int* __restrict__ rows, const int* __restrict__ cols,
                               const float* __restrict__ vals) {
    int e = blockIdx.x * blockDim.x + threadIdx.x;
    if (e >= NNZ) return;
    int idx = atomicAdd(&g_u_cursor[rows[e]], 1);
    g_u_edges[idx] = make_int2(cols[e], __float_as_int(vals[e]));
}

// ---------------- hop kernels: warp-per-row gather + register accumulate,
//                  fused normalize + residual (+ next-hop write) ----------------
template<bool FIRST>
__global__ void kg_agg_kernel(const float* __restrict__ src,
                              const float* __restrict__ wt,
                              const float* __restrict__ base,   // entity_emb (FIRST only)
                              float* __restrict__ res,
                              float* __restrict__ cur_out) {    // g_ent_next (FIRST only)
    __shared__ float s_w[N_RELATIONS * CH];
    __shared__ int   s_pk[8][32];
    __shared__ float s_mk[8][32];
    for (int i = threadIdx.x; i < N_RELATIONS * CH; i += blockDim.x) s_w[i] = wt[i];
    __syncthreads();

    int wslot = threadIdx.x >> 5, lane = threadIdx.x & 31;
    int row = blockIdx.x * 8 + wslot;                 // 100000 = 12500*8, always valid
    int s = g_kg_start[row], e = g_kg_start[row + 1];

    float2 acc = make_float2(0.f, 0.f);
    for (int b = s; b < e; b += 32) {
        int j = b + lane;
        int2 ed = (j < e) ? g_kg_edges[j] : make_int2(0, 0);
        s_pk[wslot][lane] = ed.x;
        s_mk[wslot][lane] = __int_as_float(ed.y);
        __syncwarp();
        int cnt = min(32, e - b);
        #pragma unroll 4
        for (int k = 0; k < cnt; k++) {
            int   pk = s_pk[wslot][k];
            float mk = s_mk[wslot][k];
            int t = pk & 0xFFFFF;
            int r = pk >> 20;
            float2 v = *reinterpret_cast<const float2*>(src + (size_t)t * CH + lane * 2);
            float2 w = *reinterpret_cast<const float2*>(s_w + r * CH + lane * 2);
            acc.x += v.x * (mk * w.x);
            acc.y += v.y * (mk * w.y);
        }
        __syncwarp();
    }

    float ss = acc.x * acc.x + acc.y * acc.y;
    #pragma unroll
    for (int o = 16; o; o >>= 1) ss += __shfl_xor_sync(0xffffffffu, ss, o);
    float inv = 1.0f / fmaxf(sqrtf(ss), 1e-12f);
    float2 nrm = make_float2(acc.x * inv, acc.y * inv);

    size_t off = (size_t)row * CH + lane * 2;
    if (FIRST) {
        float2 bv = *reinterpret_cast<const float2*>(base + off);
        *reinterpret_cast<float2*>(res + off) = make_float2(bv.x + nrm.x, bv.y + nrm.y);
        *reinterpret_cast<float2*>(cur_out + off) = nrm;
    } else {
        float2 rv = *reinterpret_cast<float2*>(res + off);
        *reinterpret_cast<float2*>(res + off) = make_float2(rv.x + nrm.x, rv.y + nrm.y);
    }
}

template<bool FIRST>
__global__ void u_agg_kernel(const float* __restrict__ src,
                             const float* __restrict__ base,    // user_emb (FIRST only)
                             float* __restrict__ res) {
    __shared__ int   s_c[8][32];
    __shared__ float s_v[8][32];
    int wslot = threadIdx.x >> 5, lane = threadIdx.x & 31;
    int row = blockIdx.x * 8 + wslot;                 // 50000 = 6250*8, always valid
    int s = g_u_start[row], e = g_u_start[row + 1];

    float2 acc = make_float2(0.f, 0.f);
    for (int b = s; b < e; b += 32) {
        int j = b + lane;
        int2 ed = (j < e) ? g_u_edges[j] : make_int2(0, 0);
        s_c[wslot][lane] = ed.x;
        s_v[wslot][lane] = __int_as_float(ed.y);
        __syncwarp();
        int cnt = min(32, e - b);
        #pragma unroll 4
        for (int k = 0; k < cnt; k++) {
            int   c  = s_c[wslot][k];
            float vv = s_v[wslot][k];
            float2 v = *reinterpret_cast<const float2*>(src + (size_t)c * CH + lane * 2);
            acc.x += v.x * vv;
            acc.y += v.y * vv;
        }
        __syncwarp();
    }

    float ss = acc.x * acc.x + acc.y * acc.y;
    #pragma unroll
    for (int o = 16; o; o >>= 1) ss += __shfl_xor_sync(0xffffffffu, ss, o);
    float inv = 1.0f / fmaxf(sqrtf(ss), 1e-12f);
    float2 nrm = make_float2(acc.x * inv, acc.y * inv);

    size_t off = (size_t)row * CH + lane * 2;
    if (FIRST) {
        float2 bv = *reinterpret_cast<const float2*>(base + off);
        *reinterpret_cast<float2*>(res + off) = make_float2(bv.x + nrm.x, bv.y + nrm.y);
    } else {
        float2 rv = *reinterpret_cast<float2*>(res + off);
        *reinterpret_cast<float2*>(res + off) = make_float2(rv.x + nrm.x, rv.y + nrm.y);
    }
}

// ---------------- launch ----------------
extern "C" void kernel_launch(void* const* d_in, const int* in_sizes, int n_in,
                              void* d_out, int out_size) {
    const float* user_emb   = (const float*)d_in[0];
    const float* entity_emb = (const float*)d_in[1];
    const float* weight     = (const float*)d_in[2];
    const float* mask       = (const float*)d_in[3];
    const float* ivals      = (const float*)d_in[4];
    const int*   ehead      = (const int*)d_in[5];
    const int*   etail      = (const int*)d_in[6];
    const int*   etype      = (const int*)d_in[7];
    const int*   irows      = (const int*)d_in[8];
    const int*   icols      = (const int*)d_in[9];

    float* out     = (float*)d_out;
    float* ent_res = out;
    float* usr_res = out + (size_t)N_ENTITIES * CH;

    void* p;
    cudaGetSymbolAddress(&p, g_kg_cursor); int* kg_cur = (int*)p;
    cudaGetSymbolAddress(&p, g_u_cursor);  int* u_cur  = (int*)p;
    cudaGetSymbolAddress(&p, g_ent_next);  float* ent_next = (float*)p;

    const int TPB = 256;

    // --- preprocessing: CSR grouping (once per call, reused by both hops) ---
    cudaMemsetAsync(kg_cur, 0, N_ENTITIES * sizeof(int));
    cudaMemsetAsync(u_cur,  0, N_USERS * sizeof(int));
    hist_kernel<<<(N_EDGES + TPB - 1) / TPB, TPB>>>(ehead, N_EDGES, kg_cur);
    hist_kernel<<<(NNZ + TPB - 1) / TPB, TPB>>>(irows, NNZ, u_cur);
    scan2_kernel<<<2, 1024>>>();
    kg_build_kernel<<<(N_EDGES + TPB - 1) / TPB, TPB>>>(ehead, etail, etype, mask);
    u_build_kernel<<<(NNZ + TPB - 1) / TPB, TPB>>>(irows, icols, ivals);

    // --- hop 0: read raw entity_emb, write normalized entity to g_ent_next,
    //            residuals = base + normalized ---
    kg_agg_kernel<true><<<N_ENTITIES / 8, TPB>>>(entity_emb, weight, entity_emb, ent_res, ent_next);
    u_agg_kernel<true><<<N_USERS / 8, TPB>>>(entity_emb, user_emb, usr_res);

    // --- hop 1: read g_ent_next, accumulate into residuals (no cur output needed) ---
    kg_agg_kernel<false><<<N_ENTITIES / 8, TPB>>>(ent_next, weight, nullptr, ent_res, nullptr);
    u_agg_kernel<false><<<N_USERS / 8, TPB>>>(ent_next, nullptr, usr_res);
}

// round 3
// speedup vs baseline: 1.7844x; 1.0698x over previous
#include <cuda_runtime.h>
#include <cstdint>

#define N_USERS     50000
#define N_ENTITIES  100000
#define N_RELATIONS 16
#define N_EDGES     3200000
#define NNZ         2500000
#define CH          64
#define N_HOPS      2
#define N_ROWS_ALL  (N_ENTITIES + N_USERS)

// ---------------- scratch (__device__ globals, allocation-free) ----------------
__device__ __align__(16) float g_ent_next[(size_t)N_ENTITIES * CH];

__device__ int  g_kg_start[N_ENTITIES + 1];
__device__ int  g_kg_cursor[N_ENTITIES];
__device__ __align__(16) int2 g_kg_edges[N_EDGES];   // {tail | rel<<20, mask_bits}

__device__ int  g_u_start[N_USERS + 1];
__device__ int  g_u_cursor[N_USERS];
__device__ __align__(16) int2 g_u_edges[NNZ];        // {col, val_bits}

// ---------------- preprocessing: fused histogram ----------------
__global__ void hist_kernel(const int* __restrict__ ehead, const int* __restrict__ irows) {
    int i = blockIdx.x * blockDim.x + threadIdx.x;
    if (i < N_EDGES) {
        atomicAdd(&g_kg_cursor[ehead[i]], 1);
    } else if (i < N_EDGES + NNZ) {
        atomicAdd(&g_u_cursor[irows[i - N_EDGES]], 1);
    }
}

// ---------------- exclusive scan (block 0 -> KG, block 1 -> user) ----------------
__global__ void scan2_kernel() {
    int* cnt   = (blockIdx.x == 0) ? g_kg_cursor : g_u_cursor;
    int* start = (blockIdx.x == 0) ? g_kg_start  : g_u_start;
    int  n     = (blockIdx.x == 0) ? N_ENTITIES  : N_USERS;

    __shared__ int s_wsum[32];
    __shared__ int s_carry;
    int lane = threadIdx.x & 31, wid = threadIdx.x >> 5;
    if (threadIdx.x == 0) s_carry = 0;
    __syncthreads();

    for (int base = 0; base < n; base += 1024) {
        int i = base + threadIdx.x;
        int v = (i < n) ? cnt[i] : 0;
        int x = v;
        #pragma unroll
        for (int off = 1; off < 32; off <<= 1) {
            int y = __shfl_up_sync(0xffffffffu, x, off);
            if (lane >= off) x += y;
        }
        if (lane == 31) s_wsum[wid] = x;
        __syncthreads();
        int carry = s_carry;
        __syncthreads();
        if (wid == 0) {
            int ws = s_wsum[lane];
            int wx = ws;
            #pragma unroll
            for (int off = 1; off < 32; off <<= 1) {
                int y = __shfl_up_sync(0xffffffffu, wx, off);
                if (lane >= off) wx += y;
            }
            s_wsum[lane] = wx - ws;
            if (lane == 31) s_carry = carry + wx;
        }
        __syncthreads();
        int excl = carry + s_wsum[wid] + x - v;
        if (i < n) { start[i] = excl; cnt[i] = excl; }
        __syncthreads();
    }
    if (threadIdx.x == 0) start[n] = s_carry;
}

// ---------------- preprocessing: fused bucket-scatter ----------------
__global__ void build_kernel(const int* __restrict__ head, const int* __restrict__ tail,
                             const int* __restrict__ etype, const float* __restrict__ mask,
                             const int* __restrict__ rows, const int* __restrict__ cols,
                             const float* __restrict__ vals) {
    int i = blockIdx.x * blockDim.x + threadIdx.x;
    if (i < N_EDGES) {
        int idx = atomicAdd(&g_kg_cursor[head[i]], 1);
        g_kg_edges[idx] = make_int2(tail[i] | ((etype[i] - 1) << 20), __float_as_int(mask[i]));
    } else if (i < N_EDGES + NNZ) {
        int j = i - N_EDGES;
        int idx = atomicAdd(&g_u_cursor[rows[j]], 1);
        g_u_edges[idx] = make_int2(cols[j], __float_as_int(vals[j]));
    }
}

// ---------------- merged hop kernel ----------------
// One warp per output row (KG rows 0..N_ENTITIES-1, user rows after).
// Half-warps process alternating edges; each lane holds float4 (4 channels).
template<bool FIRST>
__global__ void __launch_bounds__(256) hop_kernel(
        const float* __restrict__ src,        // entity table to gather from
        const float* __restrict__ wt,
        const float* __restrict__ ebase,      // entity_emb (FIRST only)
        const float* __restrict__ ubase,      // user_emb   (FIRST only)
        float* __restrict__ ent_res,
        float* __restrict__ usr_res,
        float* __restrict__ ent_next) {       // FIRST only
    __shared__ float4 s_w[N_RELATIONS * 16];
    __shared__ int2   s_ed[8][32];
    for (int i = threadIdx.x; i < N_RELATIONS * 16; i += blockDim.x)
        s_w[i] = reinterpret_cast<const float4*>(wt)[i];
    __syncthreads();

    int wslot = threadIdx.x >> 5, lane = threadIdx.x & 31;
    int half = lane >> 4, hl = lane & 15;
    int row = blockIdx.x * 8 + wslot;               // 150000 = 18750*8
    bool is_kg = row < N_ENTITIES;
    int urow = row - N_ENTITIES;

    int s, e;
    const int2* __restrict__ edges;
    if (is_kg) { s = g_kg_start[row];  e = g_kg_start[row + 1];  edges = g_kg_edges; }
    else       { s = g_u_start[urow];  e = g_u_start[urow + 1];  edges = g_u_edges; }

    float4 acc = make_float4(0.f, 0.f, 0.f, 0.f);
    for (int b = s; b < e; b += 32) {
        int j = b + lane;
        s_ed[wslot][lane] = (j < e) ? edges[j] : make_int2(0, 0);
        __syncwarp();
        int cnt = min(32, e - b);
        if (is_kg) {
            #pragma unroll 4
            for (int k = 0; k < cnt; k += 2) {
                int kk = k + half;
                if (kk < cnt) {
                    int2 ed = s_ed[wslot][kk];
                    int   t = ed.x & 0xFFFFF;
                    int   r = ed.x >> 20;
                    float m = __int_as_float(ed.y);
                    float4 v = *reinterpret_cast<const float4*>(src + (size_t)t * CH + hl * 4);
                    float4 w = s_w[r * 16 + hl];
                    acc.x += v.x * (m * w.x);
                    acc.y += v.y * (m * w.y);
                    acc.z += v.z * (m * w.z);
                    acc.w += v.w * (m * w.w);
                }
            }
        } else {
            #pragma unroll 4
            for (int k = 0; k < cnt; k += 2) {
                int kk = k + half;
                if (kk < cnt) {
                    int2 ed = s_ed[wslot][kk];
                    float vv = __int_as_float(ed.y);
                    float4 v = *reinterpret_cast<const float4*>(src + (size_t)ed.x * CH + hl * 4);
                    acc.x += v.x * vv;
                    acc.y += v.y * vv;
                    acc.z += v.z * vv;
                    acc.w += v.w * vv;
                }
            }
        }
        __syncwarp();
    }

    // combine even/odd-edge halves (lane hl and lane 16+hl hold the same channels)
    acc.x += __shfl_xor_sync(0xffffffffu, acc.x, 16);
    acc.y += __shfl_xor_sync(0xffffffffu, acc.y, 16);
    acc.z += __shfl_xor_sync(0xffffffffu, acc.z, 16);
    acc.w += __shfl_xor_sync(0xffffffffu, acc.w, 16);

    // L2 norm over 64 channels: reduce within 16-lane group
    float ss = acc.x * acc.x + acc.y * acc.y + acc.z * acc.z + acc.w * acc.w;
    #pragma unroll
    for (int o = 8; o; o >>= 1) ss += __shfl_xor_sync(0xffffffffu, ss, o);
    float inv = 1.0f / fmaxf(sqrtf(ss), 1e-12f);
    float4 nrm = make_float4(acc.x * inv, acc.y * inv, acc.z * inv, acc.w * inv);

    if (half == 0) {
        if (is_kg) {
            size_t off = (size_t)row * CH + hl * 4;
            if (FIRST) {
                float4 bv = *reinterpret_cast<const float4*>(ebase + off);
                *reinterpret_cast<float4*>(ent_res + off) =
                    make_float4(bv.x + nrm.x, bv.y + nrm.y, bv.z + nrm.z, bv.w + nrm.w);
                *reinterpret_cast<float4*>(ent_next + off) = nrm;
            } else {
                float4 rv = *reinterpret_cast<float4*>(ent_res + off);
                *reinterpret_cast<float4*>(ent_res + off) =
                    make_float4(rv.x + nrm.x, rv.y + nrm.y, rv.z + nrm.z, rv.w + nrm.w);
            }
        } else {
            size_t off = (size_t)urow * CH + hl * 4;
            if (FIRST) {
                float4 bv = *reinterpret_cast<const float4*>(ubase + off);
                *reinterpret_cast<float4*>(usr_res + off) =
                    make_float4(bv.x + nrm.x, bv.y + nrm.y, bv.z + nrm.z, bv.w + nrm.w);
            } else {
                float4 rv = *reinterpret_cast<float4*>(usr_res + off);
                *reinterpret_cast<float4*>(usr_res + off) =
                    make_float4(rv.x + nrm.x, rv.y + nrm.y, rv.z + nrm.z, rv.w + nrm.w);
            }
        }
    }
}

// ---------------- launch ----------------
extern "C" void kernel_launch(void* const* d_in, const int* in_sizes, int n_in,
                              void* d_out, int out_size) {
    const float* user_emb   = (const float*)d_in[0];
    const float* entity_emb = (const float*)d_in[1];
    const float* weight     = (const float*)d_in[2];
    const float* mask       = (const float*)d_in[3];
    const float* ivals      = (const float*)d_in[4];
    const int*   ehead      = (const int*)d_in[5];
    const int*   etail      = (const int*)d_in[6];
    const int*   etype      = (const int*)d_in[7];
    const int*   irows      = (const int*)d_in[8];
    const int*   icols      = (const int*)d_in[9];

    float* out     = (float*)d_out;
    float* ent_res = out;
    float* usr_res = out + (size_t)N_ENTITIES * CH;

    void* p;
    cudaGetSymbolAddress(&p, g_kg_cursor); int* kg_cur = (int*)p;
    cudaGetSymbolAddress(&p, g_u_cursor);  int* u_cur  = (int*)p;
    cudaGetSymbolAddress(&p, g_ent_next);  float* ent_next = (float*)p;

    const int TPB = 256;
    const int n_total = N_EDGES + NNZ;

    // --- preprocessing: CSR grouping ---
    cudaMemsetAsync(kg_cur, 0, N_ENTITIES * sizeof(int));
    cudaMemsetAsync(u_cur,  0, N_USERS * sizeof(int));
    hist_kernel<<<(n_total + TPB - 1) / TPB, TPB>>>(ehead, irows);
    scan2_kernel<<<2, 1024>>>();
    build_kernel<<<(n_total + TPB - 1) / TPB, TPB>>>(ehead, etail, etype, mask,
                                                     irows, icols, ivals);

    // --- hop 0: gather raw entity_emb; residual = base + normalized; next = normalized ---
    hop_kernel<true><<<N_ROWS_ALL / 8, TPB>>>(entity_emb, weight, entity_emb, user_emb,
                                              ent_res, usr_res, ent_next);
    // --- hop 1: gather g_ent_next; residual += normalized ---
    hop_kernel<false><<<N_ROWS_ALL / 8, TPB>>>(ent_next, weight, nullptr, nullptr,
                                               ent_res, usr_res, nullptr);
}

// round 4
// speedup vs baseline: 1.9389x; 1.0866x over previous
#include <cuda_runtime.h>
#include <cstdint>

#define N_USERS     50000
#define N_ENTITIES  100000
#define N_RELATIONS 16
#define N_EDGES     3200000
#define NNZ         2500000
#define CH          64
#define N_ROWS_ALL  (N_ENTITIES + N_USERS)

// hop-kernel row mapping: each warp handles R_PER_WARP strided rows
#define R_PER_WARP  4
#define HOP_BLOCKS  4688                       // 4688*8 = 37504 warps
#define TOT_WARPS   (HOP_BLOCKS * 8)

// ---------------- scratch (__device__ globals, allocation-free) ----------------
__device__ __align__(16) float g_ent_next[(size_t)N_ENTITIES * CH];

__device__ int  g_kg_start[N_ENTITIES + 1];
__device__ int  g_kg_cursor[N_ENTITIES];
__device__ __align__(16) int2 g_kg_edges[N_EDGES];   // {tail*CH | rel, mask_bits}

__device__ int  g_u_start[N_USERS + 1];
__device__ int  g_u_cursor[N_USERS];
__device__ __align__(16) int2 g_u_edges[NNZ];        // {col*CH, val_bits}

// ---------------- preprocessing: fused histogram ----------------
__global__ void hist_kernel(const int* __restrict__ ehead, const int* __restrict__ irows) {
    int i = blockIdx.x * blockDim.x + threadIdx.x;
    if (i < N_EDGES) {
        atomicAdd(&g_kg_cursor[ehead[i]], 1);
    } else if (i < N_EDGES + NNZ) {
        atomicAdd(&g_u_cursor[irows[i - N_EDGES]], 1);
    }
}

// ---------------- exclusive scan (block 0 -> KG, block 1 -> user) ----------------
__global__ void scan2_kernel() {
    int* cnt   = (blockIdx.x == 0) ? g_kg_cursor : g_u_cursor;
    int* start = (blockIdx.x == 0) ? g_kg_start  : g_u_start;
    int  n     = (blockIdx.x == 0) ? N_ENTITIES  : N_USERS;

    __shared__ int s_wsum[32];
    __shared__ int s_carry;
    int lane = threadIdx.x & 31, wid = threadIdx.x >> 5;
    if (threadIdx.x == 0) s_carry = 0;
    __syncthreads();

    for (int base = 0; base < n; base += 1024) {
        int i = base + threadIdx.x;
        int v = (i < n) ? cnt[i] : 0;
        int x = v;
        #pragma unroll
        for (int off = 1; off < 32; off <<= 1) {
            int y = __shfl_up_sync(0xffffffffu, x, off);
            if (lane >= off) x += y;
        }
        if (lane == 31) s_wsum[wid] = x;
        __syncthreads();
        int carry = s_carry;
        __syncthreads();
        if (wid == 0) {
            int ws = s_wsum[lane];
            int wx = ws;
            #pragma unroll
            for (int off = 1; off < 32; off <<= 1) {
                int y = __shfl_up_sync(0xffffffffu, wx, off);
                if (lane >= off) wx += y;
            }
            s_wsum[lane] = wx - ws;
            if (lane == 31) s_carry = carry + wx;
        }
        __syncthreads();
        int excl = carry + s_wsum[wid] + x - v;
        if (i < n) { start[i] = excl; cnt[i] = excl; }
        __syncthreads();
    }
    if (threadIdx.x == 0) start[n] = s_carry;
}

// ---------------- preprocessing: fused bucket-scatter (pre-scaled indices) ----------------
__global__ void build_kernel(const int* __restrict__ head, const int* __restrict__ tail,
                             const int* __restrict__ etype, const float* __restrict__ mask,
                             const int* __restrict__ rows, const int* __restrict__ cols,
                             const float* __restrict__ vals) {
    int i = blockIdx.x * blockDim.x + threadIdx.x;
    if (i < N_EDGES) {
        int idx = atomicAdd(&g_kg_cursor[head[i]], 1);
        // tail*CH has 6 low zero bits; rel (0..15) packs into low 4
        g_kg_edges[idx] = make_int2((tail[i] * CH) | (etype[i] - 1), __float_as_int(mask[i]));
    } else if (i < N_EDGES + NNZ) {
        int j = i - N_EDGES;
        int idx = atomicAdd(&g_u_cursor[rows[j]], 1);
        g_u_edges[idx] = make_int2(cols[j] * CH, __float_as_int(vals[j]));
    }
}

// ---------------- merged hop kernel ----------------
// Each warp handles R_PER_WARP strided rows; half-warps split the edges of a
// row; each lane accumulates float4 (4 channels). Full 32-edge tiles run
// predicate-free; only the tail tile carries bounds checks.
template<bool FIRST>
__global__ void __launch_bounds__(256) hop_kernel(
        const float* __restrict__ src,
        const float* __restrict__ wt,
        const float* __restrict__ ebase,
        const float* __restrict__ ubase,
        float* __restrict__ ent_res,
        float* __restrict__ usr_res,
        float* __restrict__ ent_next) {
    __shared__ float4 s_w[N_RELATIONS * 16];
    __shared__ int2   s_ed[8][32];
    for (int i = threadIdx.x; i < N_RELATIONS * 16; i += blockDim.x)
        s_w[i] = reinterpret_cast<const float4*>(wt)[i];
    __syncthreads();

    int wslot = threadIdx.x >> 5, lane = threadIdx.x & 31;
    int half = lane >> 4, hl = lane & 15;
    int wg = blockIdx.x * 8 + wslot;

    #pragma unroll 1
    for (int rr = 0; rr < R_PER_WARP; rr++) {
        int row = wg + rr * TOT_WARPS;
        if (row >= N_ROWS_ALL) break;
        bool is_kg = row < N_ENTITIES;
        int urow = row - N_ENTITIES;

        int s, e;
        const int2* __restrict__ edges;
        if (is_kg) { s = g_kg_start[row];  e = g_kg_start[row + 1];  edges = g_kg_edges; }
        else       { s = g_u_start[urow];  e = g_u_start[urow + 1];  edges = g_u_edges; }

        float4 acc = make_float4(0.f, 0.f, 0.f, 0.f);
        int b = s;

        // --- full 32-edge tiles: no predicates ---
        for (; b + 32 <= e; b += 32) {
            s_ed[wslot][lane] = edges[b + lane];
            __syncwarp();
            if (is_kg) {
                #pragma unroll 8
                for (int k = half; k < 32; k += 2) {
                    int2 ed = s_ed[wslot][k];
                    float m = __int_as_float(ed.y);
                    float4 v = *reinterpret_cast<const float4*>(src + (ed.x & ~15) + hl * 4);
                    float4 w = s_w[(ed.x & 15) * 16 + hl];
                    acc.x += v.x * (m * w.x);
                    acc.y += v.y * (m * w.y);
                    acc.z += v.z * (m * w.z);
                    acc.w += v.w * (m * w.w);
                }
            } else {
                #pragma unroll 8
                for (int k = half; k < 32; k += 2) {
                    int2 ed = s_ed[wslot][k];
                    float vv = __int_as_float(ed.y);
                    float4 v = *reinterpret_cast<const float4*>(src + ed.x + hl * 4);
                    acc.x += v.x * vv;
                    acc.y += v.y * vv;
                    acc.z += v.z * vv;
                    acc.w += v.w * vv;
                }
            }
            __syncwarp();
        }

        // --- tail tile ---
        if (b < e) {
            int j = b + lane;
            s_ed[wslot][lane] = (j < e) ? edges[j] : make_int2(0, 0);
            __syncwarp();
            int cnt = e - b;
            if (is_kg) {
                for (int k = half; k < cnt; k += 2) {
                    int2 ed = s_ed[wslot][k];
                    float m = __int_as_float(ed.y);
                    float4 v = *reinterpret_cast<const float4*>(src + (ed.x & ~15) + hl * 4);
                    float4 w = s_w[(ed.x & 15) * 16 + hl];
                    acc.x += v.x * (m * w.x);
                    acc.y += v.y * (m * w.y);
                    acc.z += v.z * (m * w.z);
                    acc.w += v.w * (m * w.w);
                }
            } else {
                for (int k = half; k < cnt; k += 2) {
                    int2 ed = s_ed[wslot][k];
                    float vv = __int_as_float(ed.y);
                    float4 v = *reinterpret_cast<const float4*>(src + ed.x + hl * 4);
                    acc.x += v.x * vv;
                    acc.y += v.y * vv;
                    acc.z += v.z * vv;
                    acc.w += v.w * vv;
                }
            }
            __syncwarp();
        }

        // combine the two half-warp partial sums (same channels, lanes hl and hl+16)
        acc.x += __shfl_xor_sync(0xffffffffu, acc.x, 16);
        acc.y += __shfl_xor_sync(0xffffffffu, acc.y, 16);
        acc.z += __shfl_xor_sync(0xffffffffu, acc.z, 16);
        acc.w += __shfl_xor_sync(0xffffffffu, acc.w, 16);

        // L2 norm over 64 channels within 16-lane group
        float ss = acc.x * acc.x + acc.y * acc.y + acc.z * acc.z + acc.w * acc.w;
        #pragma unroll
        for (int o = 8; o; o >>= 1) ss += __shfl_xor_sync(0xffffffffu, ss, o);
        float inv = 1.0f / fmaxf(sqrtf(ss), 1e-12f);
        float4 nrm = make_float4(acc.x * inv, acc.y * inv, acc.z * inv, acc.w * inv);

        if (half == 0) {
            if (is_kg) {
                size_t off = (size_t)row * CH + hl * 4;
                if (FIRST) {
                    float4 bv = *reinterpret_cast<const float4*>(ebase + off);
                    *reinterpret_cast<float4*>(ent_res + off) =
                        make_float4(bv.x + nrm.x, bv.y + nrm.y, bv.z + nrm.z, bv.w + nrm.w);
                    *reinterpret_cast<float4*>(ent_next + off) = nrm;
                } else {
                    float4 rv = *reinterpret_cast<float4*>(ent_res + off);
                    *reinterpret_cast<float4*>(ent_res + off) =
                        make_float4(rv.x + nrm.x, rv.y + nrm.y, rv.z + nrm.z, rv.w + nrm.w);
                }
            } else {
                size_t off = (size_t)urow * CH + hl * 4;
                if (FIRST) {
                    float4 bv = *reinterpret_cast<const float4*>(ubase + off);
                    *reinterpret_cast<float4*>(usr_res + off) =
                        make_float4(bv.x + nrm.x, bv.y + nrm.y, bv.z + nrm.z, bv.w + nrm.w);
                } else {
                    float4 rv = *reinterpret_cast<float4*>(usr_res + off);
                    *reinterpret_cast<float4*>(usr_res + off) =
                        make_float4(rv.x + nrm.x, rv.y + nrm.y, rv.z + nrm.z, rv.w + nrm.w);
                }
            }
        }
    }
}

// ---------------- launch ----------------
extern "C" void kernel_launch(void* const* d_in, const int* in_sizes, int n_in,
                              void* d_out, int out_size) {
    const float* user_emb   = (const float*)d_in[0];
    const float* entity_emb = (const float*)d_in[1];
    const float* weight     = (const float*)d_in[2];
    const float* mask       = (const float*)d_in[3];
    const float* ivals      = (const float*)d_in[4];
    const int*   ehead      = (const int*)d_in[5];
    const int*   etail      = (const int*)d_in[6];
    const int*   etype      = (const int*)d_in[7];
    const int*   irows      = (const int*)d_in[8];
    const int*   icols      = (const int*)d_in[9];

    float* out     = (float*)d_out;
    float* ent_res = out;
    float* usr_res = out + (size_t)N_ENTITIES * CH;

    void* p;
    cudaGetSymbolAddress(&p, g_kg_cursor); int* kg_cur = (int*)p;
    cudaGetSymbolAddress(&p, g_u_cursor);  int* u_cur  = (int*)p;
    cudaGetSymbolAddress(&p, g_ent_next);  float* ent_next = (float*)p;

    const int TPB = 256;
    const int n_total = N_EDGES + NNZ;

    // --- preprocessing: CSR grouping ---
    cudaMemsetAsync(kg_cur, 0, N_ENTITIES * sizeof(int));
    cudaMemsetAsync(u_cur,  0, N_USERS * sizeof(int));
    hist_kernel<<<(n_total + TPB - 1) / TPB, TPB>>>(ehead, irows);
    scan2_kernel<<<2, 1024>>>();
    build_kernel<<<(n_total + TPB - 1) / TPB, TPB>>>(ehead, etail, etype, mask,
                                                     irows, icols, ivals);

    // --- hop 0 ---
    hop_kernel<true><<<HOP_BLOCKS, TPB>>>(entity_emb, weight, entity_emb, user_emb,
                                          ent_res, usr_res, ent_next);
    // --- hop 1 ---
    hop_kernel<false><<<HOP_BLOCKS, TPB>>>(ent_next, weight, nullptr, nullptr,
                                           ent_res, usr_res, nullptr);
}